// round 1
// baseline (speedup 1.0000x reference)
#include <cuda_runtime.h>

#define B 8
#define T_IN 512
#define D 384
#define T_MEL 3584
#define MEL_MAX 2048

// scratch: token index per mel frame (-1 = no token / beyond total)
__device__ int g_idx[B * MEL_MAX];

// Kernel A: per-batch scan + pitch averaging + frame->token map + dec_lens
__global__ void __launch_bounds__(T_IN) prep_kernel(const int* __restrict__ dur,
                                                    const float* __restrict__ pitch,
                                                    float* __restrict__ dec_lens_out,
                                                    float* __restrict__ pitch_avg_out) {
    const int b = blockIdx.x;
    const int t = threadIdx.x;

    __shared__ int cum[T_IN];
    const int d = dur[b * T_IN + t];
    cum[t] = d;
    __syncthreads();
    // Hillis-Steele inclusive scan
    #pragma unroll
    for (int off = 1; off < T_IN; off <<= 1) {
        int v = (t >= off) ? cum[t - off] : 0;
        __syncthreads();
        cum[t] += v;
        __syncthreads();
    }
    const int end = cum[t];
    const int start = end - d;
    const int total = cum[T_IN - 1];

    if (t == 0) {
        int dl = total < MEL_MAX ? total : MEL_MAX;
        dec_lens_out[b] = (float)dl;
    }

    // pitch average over [start, end) — N_FORMANTS = 1
    {
        const float* p = pitch + b * T_MEL;
        float s = 0.0f;
        float cnt = 0.0f;
        for (int m = start; m < end; m++) {
            float v = p[m];
            s += v;
            if (v != 0.0f) cnt += 1.0f;
        }
        pitch_avg_out[b * T_IN + t] = (cnt != 0.0f) ? (s / cnt) : 0.0f;
    }

    // init frame->token map to -1, then each token writes its range
    int* idx = g_idx + b * MEL_MAX;
    for (int m = t; m < MEL_MAX; m += T_IN) idx[m] = -1;
    __syncthreads();
    const int e = end < MEL_MAX ? end : MEL_MAX;
    for (int m = start; m < e; m++) idx[m] = t;
}

// Kernel B: gather rows. One block per output row (b, m); 96 threads x float4 = 384 floats.
__global__ void __launch_bounds__(96) gather_kernel(const float* __restrict__ enc,
                                                    float* __restrict__ out) {
    const int row = blockIdx.x;          // b * MEL_MAX + m
    const int b = row >> 11;             // MEL_MAX = 2048
    __shared__ int s_t;
    if (threadIdx.x == 0) s_t = g_idx[row];
    __syncthreads();
    const int t = s_t;

    float4 v;
    if (t >= 0) {
        v = __ldg(((const float4*)(enc + ((size_t)(b * T_IN + t)) * D)) + threadIdx.x);
    } else {
        v = make_float4(0.0f, 0.0f, 0.0f, 0.0f);
    }
    ((float4*)(out + (size_t)row * D))[threadIdx.x] = v;
}

extern "C" void kernel_launch(void* const* d_in, const int* in_sizes, int n_in,
                              void* d_out, int out_size) {
    const float* enc_out = (const float*)d_in[0];   // [B, T_IN, D]
    const int* durations = (const int*)d_in[1];     // [B, T_IN]
    const float* pitch = (const float*)d_in[2];     // [B, 1, T_MEL]

    float* out = (float*)d_out;
    float* enc_rep = out;                               // B*MEL_MAX*D
    float* dec_lens = out + (size_t)B * MEL_MAX * D;    // B
    float* pitch_avg = dec_lens + B;                    // B*T_IN

    prep_kernel<<<B, T_IN>>>(durations, pitch, dec_lens, pitch_avg);
    gather_kernel<<<B * MEL_MAX, 96>>>(enc_out, enc_rep);
}

// round 2
// speedup vs baseline: 1.2301x; 1.2301x over previous
#include <cuda_runtime.h>

#define B 8
#define T_IN 512
#define D 384
#define T_MEL 3584
#define MEL_MAX 2048
#define NVEC (B * MEL_MAX * (D / 4))   // total float4s in enc_rep = 1,572,864
#define VPR (D / 4)                     // float4s per row = 96

// scratch: token index per mel frame (-1 = no token / beyond total)
__device__ int g_idx[B * MEL_MAX];

// Kernel A: per-batch scan + pitch averaging + frame->token map + dec_lens
__global__ void __launch_bounds__(T_IN) prep_kernel(const int* __restrict__ dur,
                                                    const float* __restrict__ pitch,
                                                    float* __restrict__ dec_lens_out,
                                                    float* __restrict__ pitch_avg_out) {
    const int b = blockIdx.x;
    const int t = threadIdx.x;

    __shared__ int cum[T_IN];
    const int d = dur[b * T_IN + t];
    cum[t] = d;
    __syncthreads();
    // Hillis-Steele inclusive scan
    #pragma unroll
    for (int off = 1; off < T_IN; off <<= 1) {
        int v = (t >= off) ? cum[t - off] : 0;
        __syncthreads();
        cum[t] += v;
        __syncthreads();
    }
    const int end = cum[t];
    const int start = end - d;
    const int total = cum[T_IN - 1];

    if (t == 0) {
        int dl = total < MEL_MAX ? total : MEL_MAX;
        dec_lens_out[b] = (float)dl;
    }

    // pitch average over [start, end) — N_FORMANTS = 1
    {
        const float* p = pitch + b * T_MEL;
        float s = 0.0f;
        float cnt = 0.0f;
        for (int m = start; m < end; m++) {
            float v = p[m];
            s += v;
            if (v != 0.0f) cnt += 1.0f;
        }
        pitch_avg_out[b * T_IN + t] = (cnt != 0.0f) ? (s / cnt) : 0.0f;
    }

    // init frame->token map to -1, then each token writes its range
    int* idx = g_idx + b * MEL_MAX;
    for (int m = t; m < MEL_MAX; m += T_IN) idx[m] = -1;
    __syncthreads();
    const int e = end < MEL_MAX ? end : MEL_MAX;
    for (int m = start; m < e; m++) idx[m] = t;
}

// Kernel B: flat streaming gather. One thread per float4 of enc_rep.
// No smem, no barriers: consecutive threads cover a row (96 float4s),
// g_idx[row] load is an L1 broadcast across those threads.
__global__ void __launch_bounds__(512) gather_kernel(const float* __restrict__ enc,
                                                     float* __restrict__ out) {
    int vid = blockIdx.x * 512 + threadIdx.x;
    if (vid >= NVEC) return;
    const int row = vid / VPR;            // b * MEL_MAX + m
    const int c = vid - row * VPR;
    const int b = row >> 11;              // MEL_MAX = 2048
    const int t = __ldg(&g_idx[row]);

    float4 v;
    if (t >= 0) {
        v = __ldg((const float4*)enc + (size_t)(b * T_IN + t) * VPR + c);
    } else {
        v = make_float4(0.0f, 0.0f, 0.0f, 0.0f);
    }
    ((float4*)out)[vid] = v;
}

extern "C" void kernel_launch(void* const* d_in, const int* in_sizes, int n_in,
                              void* d_out, int out_size) {
    const float* enc_out = (const float*)d_in[0];   // [B, T_IN, D]
    const int* durations = (const int*)d_in[1];     // [B, T_IN]
    const float* pitch = (const float*)d_in[2];     // [B, 1, T_MEL]

    float* out = (float*)d_out;
    float* enc_rep = out;                               // B*MEL_MAX*D
    float* dec_lens = out + (size_t)B * MEL_MAX * D;    // B
    float* pitch_avg = dec_lens + B;                    // B*T_IN

    prep_kernel<<<B, T_IN>>>(durations, pitch, dec_lens, pitch_avg);
    gather_kernel<<<(NVEC + 511) / 512, 512>>>(enc_out, enc_rep);
}

// round 3
// speedup vs baseline: 1.3706x; 1.1142x over previous
#include <cuda_runtime.h>

#define B 8
#define T_IN 512
#define D 384
#define VPR (D / 4)          // 96 float4s per row
#define T_MEL 3584
#define MEL_MAX 2048
#define THREADS 384
#define COPY_BLOCKS 2048     // 256 per batch, 8 rows each
#define GRID (COPY_BLOCKS + B)

__global__ void __launch_bounds__(THREADS) fused_kernel(const float* __restrict__ enc,
                                                        const int* __restrict__ dur,
                                                        const float* __restrict__ pitch,
                                                        float* __restrict__ enc_rep,
                                                        float* __restrict__ dec_lens_out,
                                                        float* __restrict__ pitch_avg_out) {
    const int tid = threadIdx.x;
    const bool is_copy = blockIdx.x < COPY_BLOCKS;
    const int b = is_copy ? (blockIdx.x >> 8) : (blockIdx.x - COPY_BLOCKS);

    __shared__ int cum[T_IN + 1];   // cum[k] = sum of dur[0..k)
    __shared__ int wsum[4];

    // ---- two-level scan of this batch's 512 durations (threads 0..127, 4 elems each) ----
    int s0 = 0, s1 = 0, s2 = 0, s3 = 0, v = 0;
    const bool active = tid < 128;
    if (active) {
        int4 dv = ((const int4*)(dur + b * T_IN))[tid];
        s0 = dv.x; s1 = s0 + dv.y; s2 = s1 + dv.z; s3 = s2 + dv.w;
        v = s3;
        const int lane = tid & 31;
        #pragma unroll
        for (int off = 1; off < 32; off <<= 1) {
            int n = __shfl_up_sync(0xffffffffu, v, off);
            if (lane >= off) v += n;
        }
        if (lane == 31) wsum[tid >> 5] = v;   // warp total
    }
    __syncthreads();
    if (active) {
        const int wid = tid >> 5;
        int woff = 0;
        #pragma unroll
        for (int w = 0; w < 4; w++) if (w < wid) woff += wsum[w];
        const int base = woff + v - s3;       // exclusive prefix of this chunk
        cum[4 * tid + 1] = base + s0;
        cum[4 * tid + 2] = base + s1;
        cum[4 * tid + 3] = base + s2;
        cum[4 * tid + 4] = base + s3;
        if (tid == 0) cum[0] = 0;
    }
    __syncthreads();

    if (is_copy) {
        // ---- copy 8 rows: 4 row-groups of 96 lanes, 2 iterations ----
        const int lane = tid % VPR;
        const int rsub = tid / VPR;               // 0..3
        const int row_base = (blockIdx.x & 255) * 8;
        const int total = cum[T_IN];
        const float4* encb = (const float4*)enc + (size_t)b * T_IN * VPR;
        float4* outb = (float4*)enc_rep + (size_t)b * MEL_MAX * VPR;
        #pragma unroll
        for (int i = 0; i < 2; i++) {
            const int m = row_base + rsub + 4 * i;
            float4 val = make_float4(0.f, 0.f, 0.f, 0.f);
            if (m < total) {
                // last t with cum[t] <= m  (then cum[t+1] > m)
                int lo = 0, hi = T_IN;
                #pragma unroll
                for (int s = 0; s < 9; s++) {
                    int mid = (lo + hi) >> 1;
                    if (cum[mid] <= m) lo = mid; else hi = mid;
                }
                val = __ldg(encb + (size_t)lo * VPR + lane);
            }
            outb[(size_t)m * VPR + lane] = val;
        }
    } else {
        // ---- prep: pitch averaging (2 tokens per thread max) + dec_lens ----
        if (tid == 0) {
            const int total = cum[T_IN];
            dec_lens_out[b] = (float)(total < MEL_MAX ? total : MEL_MAX);
        }
        const float* p = pitch + (size_t)b * T_MEL;
        #pragma unroll
        for (int k = 0; k < 2; k++) {
            const int t = tid + k * THREADS;
            if (t < T_IN) {
                const int start = cum[t];
                const int end = cum[t + 1];
                float s = 0.0f, cnt = 0.0f;
                for (int m = start; m < end; m++) {
                    float pv = __ldg(&p[m]);
                    s += pv;
                    if (pv != 0.0f) cnt += 1.0f;
                }
                pitch_avg_out[b * T_IN + t] = (cnt != 0.0f) ? (s / cnt) : 0.0f;
            }
        }
    }
}

extern "C" void kernel_launch(void* const* d_in, const int* in_sizes, int n_in,
                              void* d_out, int out_size) {
    const float* enc_out = (const float*)d_in[0];   // [B, T_IN, D]
    const int* durations = (const int*)d_in[1];     // [B, T_IN]
    const float* pitch = (const float*)d_in[2];     // [B, 1, T_MEL]

    float* out = (float*)d_out;
    float* enc_rep = out;                               // B*MEL_MAX*D
    float* dec_lens = out + (size_t)B * MEL_MAX * D;    // B
    float* pitch_avg = dec_lens + B;                    // B*T_IN

    fused_kernel<<<GRID, THREADS>>>(enc_out, durations, pitch,
                                    enc_rep, dec_lens, pitch_avg);
}